// round 2
// baseline (speedup 1.0000x reference)
#include <cuda_runtime.h>
#include <cuda_bf16.h>

// CustomEmbedding: out[tok,:] = (x[tok] < 1000) ? sin((x/1000)*(d+1)) : weight[x,:]
// x: (32768,) int32 | weight: (50000,512) f32 | out: (32768,512) f32
// 256-thread block handles 2 tokens; each 128-thread half copies one 2KB row
// as 128 float4 (fully coalesced). Numeric ids (<1000) compute sinusoid.

#define DIM 512
#define VEC (DIM / 4)     // 128 float4 per row
#define NUM_NUM 1000
#define TOK_PER_BLK 2

__global__ void __launch_bounds__(256) custom_embedding_kernel(
    const int* __restrict__ x,
    const float4* __restrict__ weight,   // (VOCAB, 128) float4
    float4* __restrict__ out,            // (NTOK, 128) float4
    int ntok)
{
    int half = threadIdx.x >> 7;                       // 0 or 1
    int tok  = blockIdx.x * TOK_PER_BLK + half;
    if (tok >= ntok) return;
    int t = threadIdx.x & 127;                         // 0..127 within row

    int id = __ldg(&x[tok]);

    if (id >= NUM_NUM) {
        // learned row: 16B vectorized coalesced gather
        out[(size_t)tok * VEC + t] = __ldg(&weight[(size_t)id * VEC + t]);
    } else {
        // sinusoidal row: sin((id/1000) * (d+1)), d = 4t .. 4t+3
        float s = (float)id * 1e-3f;
        int d0 = t * 4;
        float4 v;
        v.x = sinf(s * (float)(d0 + 1));
        v.y = sinf(s * (float)(d0 + 2));
        v.z = sinf(s * (float)(d0 + 3));
        v.w = sinf(s * (float)(d0 + 4));
        out[(size_t)tok * VEC + t] = v;
    }
}

extern "C" void kernel_launch(void* const* d_in, const int* in_sizes, int n_in,
                              void* d_out, int out_size)
{
    // metadata order: x (int32), weight (f32), num_value (int32), is_num (bool)
    const int*    x      = (const int*)d_in[0];
    const float4* weight = (const float4*)d_in[1];
    float4*       out    = (float4*)d_out;

    int ntok = in_sizes[0];  // 32768
    int grid = (ntok + TOK_PER_BLK - 1) / TOK_PER_BLK;
    custom_embedding_kernel<<<grid, 256>>>(x, weight, out, ntok);
}

// round 3
// speedup vs baseline: 1.3039x; 1.3039x over previous
#include <cuda_runtime.h>
#include <cuda_bf16.h>

// CustomEmbedding: out[tok,:] = (x[tok] < 1000) ? sin((x/1000)*(d+1)) : weight[x,:]
// x: (32768,) int32 | weight: (50000,512) f32 | out: (32768,512) f32
//
// R2 finding: kernel is LATENCY-bound (DRAM 37%, issue 21%) with MLP=1/thread.
// New layout: 1 warp per token, each thread handles 4 float4 of the 2KB row
// (lane, lane+32, lane+64, lane+96) -> 4 independent in-flight loads per
// thread, all warp accesses fully coalesced (512B each). id load is
// warp-uniform (broadcast).

#define VEC 128            // float4 per 512-float row
#define NUM_NUM 1000
#define WARPS_PER_BLK 8    // 8 tokens per 256-thread block

__global__ void __launch_bounds__(256) custom_embedding_kernel(
    const int* __restrict__ x,
    const float4* __restrict__ weight,   // (VOCAB, 128) float4
    float4* __restrict__ out,            // (NTOK, 128) float4
    int ntok)
{
    int warp = threadIdx.x >> 5;
    int lane = threadIdx.x & 31;
    int tok  = blockIdx.x * WARPS_PER_BLK + warp;
    if (tok >= ntok) return;

    int id = __ldg(&x[tok]);             // warp-uniform broadcast load
    float4* __restrict__ dst = out + (size_t)tok * VEC;

    if (id >= NUM_NUM) {
        const float4* __restrict__ src = weight + (size_t)id * VEC;
        // 4 independent loads in flight (MLP=4), then 4 stores
        float4 a = __ldg(&src[lane]);
        float4 b = __ldg(&src[lane + 32]);
        float4 c = __ldg(&src[lane + 64]);
        float4 d = __ldg(&src[lane + 96]);
        dst[lane]      = a;
        dst[lane + 32] = b;
        dst[lane + 64] = c;
        dst[lane + 96] = d;
    } else {
        // sinusoidal row: sin((id/1000)*(dim+1)); ~3% of tokens, compute noise
        float s = (float)id * 1e-3f;
        #pragma unroll
        for (int j = 0; j < 4; j++) {
            int i  = lane + j * 32;      // float4 index within row
            int d0 = i * 4;
            float4 v;
            v.x = sinf(s * (float)(d0 + 1));
            v.y = sinf(s * (float)(d0 + 2));
            v.z = sinf(s * (float)(d0 + 3));
            v.w = sinf(s * (float)(d0 + 4));
            dst[i] = v;
        }
    }
}

extern "C" void kernel_launch(void* const* d_in, const int* in_sizes, int n_in,
                              void* d_out, int out_size)
{
    // metadata order: x (int32), weight (f32), num_value (int32), is_num (bool)
    const int*    x      = (const int*)d_in[0];
    const float4* weight = (const float4*)d_in[1];
    float4*       out    = (float4*)d_out;

    int ntok = in_sizes[0];  // 32768
    int grid = (ntok + WARPS_PER_BLK - 1) / WARPS_PER_BLK;  // 4096
    custom_embedding_kernel<<<grid, 256>>>(x, weight, out, ntok);
}

// round 4
// speedup vs baseline: 1.5208x; 1.1664x over previous
#include <cuda_runtime.h>
#include <cuda_bf16.h>

// CustomEmbedding: out[tok,:] = (x[tok] < 1000) ? sin((x/1000)*(d+1)) : weight[x,:]
// x: (32768,) int32 | weight: (50000,512) f32 | out: (32768,512) f32
//
// R3 finding: still latency-bound (DRAM 44%, issue 8%); dependent id load eats
// half the per-token latency. New layout: 2 tokens per warp. Both ids loaded
// up front (overlapped), then ALL 8 row loads issued unconditionally
// (ids < 1000 still index valid rows -> branch-free hot path, MLP=8/thread),
// numeric tokens patched with sinusoid before the streaming stores (__stcs:
// output is write-once; evict-first keeps the weight table L2-resident).

#define VEC 128            // float4 per 512-float row
#define NUM_NUM 1000
#define WARPS_PER_BLK 8
#define TOK_PER_WARP 2     // 16 tokens per 256-thread block

__device__ __forceinline__ void sin_row(int id, int lane, float4* v)
{
    float s = (float)id * 1e-3f;
    #pragma unroll
    for (int j = 0; j < 4; j++) {
        int d0 = (lane + j * 32) * 4;
        v[j].x = sinf(s * (float)(d0 + 1));
        v[j].y = sinf(s * (float)(d0 + 2));
        v[j].z = sinf(s * (float)(d0 + 3));
        v[j].w = sinf(s * (float)(d0 + 4));
    }
}

__global__ void __launch_bounds__(256) custom_embedding_kernel(
    const int* __restrict__ x,
    const float4* __restrict__ weight,   // (VOCAB, 128) float4
    float4* __restrict__ out,            // (NTOK, 128) float4
    int ntok)
{
    int warp = threadIdx.x >> 5;
    int lane = threadIdx.x & 31;
    int tok0 = (blockIdx.x * WARPS_PER_BLK + warp) * TOK_PER_WARP;
    if (tok0 >= ntok) return;

    // both id loads issued back-to-back (independent, latency overlapped)
    int id0 = __ldg(&x[tok0]);
    int id1 = __ldg(&x[tok0 + 1]);

    const float4* __restrict__ s0 = weight + (size_t)id0 * VEC;
    const float4* __restrict__ s1 = weight + (size_t)id1 * VEC;

    // 8 independent row loads in flight (branch-free; numeric ids read a
    // valid-but-unused row, ~3% of tokens)
    float4 v0[4], v1[4];
    v0[0] = __ldg(&s0[lane]);
    v0[1] = __ldg(&s0[lane + 32]);
    v0[2] = __ldg(&s0[lane + 64]);
    v0[3] = __ldg(&s0[lane + 96]);
    v1[0] = __ldg(&s1[lane]);
    v1[1] = __ldg(&s1[lane + 32]);
    v1[2] = __ldg(&s1[lane + 64]);
    v1[3] = __ldg(&s1[lane + 96]);

    // patch numeric tokens with the sinusoidal row
    if (id0 < NUM_NUM) sin_row(id0, lane, v0);
    if (id1 < NUM_NUM) sin_row(id1, lane, v1);

    // streaming stores (evict-first: output never re-read, protect L2 table)
    float4* __restrict__ d0 = out + (size_t)tok0 * VEC;
    float4* __restrict__ d1 = d0 + VEC;
    __stcs(&d0[lane],      v0[0]);
    __stcs(&d0[lane + 32], v0[1]);
    __stcs(&d0[lane + 64], v0[2]);
    __stcs(&d0[lane + 96], v0[3]);
    __stcs(&d1[lane],      v1[0]);
    __stcs(&d1[lane + 32], v1[1]);
    __stcs(&d1[lane + 64], v1[2]);
    __stcs(&d1[lane + 96], v1[3]);
}

extern "C" void kernel_launch(void* const* d_in, const int* in_sizes, int n_in,
                              void* d_out, int out_size)
{
    // metadata order: x (int32), weight (f32), num_value (int32), is_num (bool)
    const int*    x      = (const int*)d_in[0];
    const float4* weight = (const float4*)d_in[1];
    float4*       out    = (float4*)d_out;

    int ntok = in_sizes[0];  // 32768
    int tok_per_blk = WARPS_PER_BLK * TOK_PER_WARP;       // 16
    int grid = (ntok + tok_per_blk - 1) / tok_per_blk;    // 2048
    custom_embedding_kernel<<<grid, 256>>>(x, weight, out, ntok);
}